// round 1
// baseline (speedup 1.0000x reference)
#include <cuda_runtime.h>
#include <math.h>

#define DIMD 768
#define NTOK 1024
#define NB   16
#define MTOT (NB*NTOK)   // 16384

// scratch (static device globals — no allocations allowed)
__device__ float g_avg[NB*DIMD];
__device__ float g_A [MTOT*DIMD];
__device__ float g_sq[MTOT];
__device__ float g_m [MTOT];
__device__ float g_m1[MTOT*DIMD];
__device__ float g_t [MTOT*DIMD];

__device__ __forceinline__ float tf32r(float x){
    unsigned u; asm("cvt.rna.tf32.f32 %0, %1;" : "=r"(u) : "f"(x));
    return __uint_as_float(u);
}
__device__ __forceinline__ float gelu_exact(float v){
    return v * normcdff(v);   // x * Phi(x), exact (erf-based)
}
__device__ __forceinline__ void mma8(float* cc, const float* a, const float* b){
    asm volatile("mma.sync.aligned.m16n8k8.row.col.f32.tf32.tf32.f32 "
       "{%0,%1,%2,%3},{%4,%5,%6,%7},{%8,%9},{%0,%1,%2,%3};"
       : "+f"(cc[0]),"+f"(cc[1]),"+f"(cc[2]),"+f"(cc[3])
       : "r"(__float_as_uint(a[0])),"r"(__float_as_uint(a[1])),
         "r"(__float_as_uint(a[2])),"r"(__float_as_uint(a[3])),
         "r"(__float_as_uint(b[0])),"r"(__float_as_uint(b[1])));
}

// ---------------------------------------------------------------- k_avg
__global__ void k_avg(const float* __restrict__ x){
    int gid = blockIdx.x*256 + threadIdx.x;       // 0..12287
    int b = gid / DIMD, d = gid % DIMD;
    const float* p = x + (size_t)b*NTOK*DIMD + d;
    float s = 0.f;
    #pragma unroll 8
    for (int n = 0; n < NTOK; n++) s += p[n*DIMD];
    g_avg[gid] = s * (1.0f/NTOK);
}

// ---------------------------------------------------------------- k_ln
__global__ void k_ln(const float* __restrict__ x,
                     const float* __restrict__ gamma,
                     const float* __restrict__ beta){
    int tok = blockIdx.x;                          // 0..16383
    int b = tok >> 10;
    const float* xp = x + (size_t)tok*DIMD;
    int t = threadIdx.x;                           // 256 threads
    float v[3]; float s=0.f, s2=0.f;
    #pragma unroll
    for (int i=0;i<3;i++){ v[i]=xp[t+256*i]; s+=v[i]; s2+=v[i]*v[i]; }
    __shared__ float red[16];
    #pragma unroll
    for (int o=16;o;o>>=1){ s+=__shfl_xor_sync(~0u,s,o); s2+=__shfl_xor_sync(~0u,s2,o); }
    int w = t>>5;
    if ((t&31)==0){ red[w]=s; red[w+8]=s2; }
    __syncthreads();
    if (t<32){
        float a=(t<8)?red[t]:0.f, bb=(t<8)?red[t+8]:0.f;
        #pragma unroll
        for (int o=4;o;o>>=1){ a+=__shfl_xor_sync(~0u,a,o); bb+=__shfl_xor_sync(~0u,bb,o); }
        if (t==0){ red[0]=a; red[1]=bb; }
    }
    __syncthreads();
    float mu  = red[0]*(1.f/DIMD);
    float var = red[1]*(1.f/DIMD) - mu*mu;
    float rs  = rsqrtf(var + 1e-5f);
    float asq = 0.f;
    float* Ap = g_A + (size_t)tok*DIMD;
    const float* av = g_avg + b*DIMD;
    #pragma unroll
    for (int i=0;i<3;i++){
        int d = t + 256*i;
        float y  = (v[i]-mu)*rs*gamma[d] + beta[d];
        float sg = 1.f/(1.f+expf(-y));
        float a  = av[d]*sg;
        Ap[d] = a;
        asq += a*a;
    }
    // reduce asq
    #pragma unroll
    for (int o=16;o;o>>=1) asq += __shfl_xor_sync(~0u,asq,o);
    __syncthreads();
    if ((t&31)==0) red[w]=asq;
    __syncthreads();
    if (t==0){
        float a=0.f;
        #pragma unroll
        for (int i=0;i<8;i++) a+=red[i];
        g_sq[tok]=a;
        g_m[tok]=0.f;   // init row-max for k_gram
    }
}

// ---------------------------------------------------------------- k_gram
// per batch: row-max over j of sqrt(clip(sq_i + sq_j - 2*A_i.A_j))
__global__ void __launch_bounds__(256) k_gram(){
    int ib = blockIdx.x, jb = blockIdx.y, b = blockIdx.z;
    const float* Ab = g_A + (size_t)b*NTOK*DIMD;
    __shared__ float Is[2][128*20];
    __shared__ float Js[2][128*20];
    __shared__ float ssqi[128], ssqj[128];
    __shared__ int   smax[128];
    int tid=threadIdx.x, lane=tid&31, warp=tid>>5;
    int wm=warp&1, wn=warp>>1, r=lane>>2, c=lane&3;

    float acc[4][4][4];
    #pragma unroll
    for (int a=0;a<4;a++)
      #pragma unroll
      for (int bb=0;bb<4;bb++)
        #pragma unroll
        for (int cc=0;cc<4;cc++) acc[a][bb][cc]=0.f;

    float4 ir[2], jr[2];
    auto loadg = [&](int kt, float4* irr, float4* jrr){
        #pragma unroll
        for (int it=0; it<2; it++){
            int L=tid+it*256, row=L>>2, c4=L&3;
            int kg=kt*16+c4*4;
            irr[it] = *(const float4*)(Ab + (ib*128+row)*DIMD + kg);
            jrr[it] = *(const float4*)(Ab + (jb*128+row)*DIMD + kg);
        }
    };
    auto stores = [&](int buf, float4* irr, float4* jrr){
        #pragma unroll
        for (int it=0; it<2; it++){
            int L=tid+it*256, row=L>>2, c4=L&3;
            float* p=&Is[buf][row*20+c4*4];
            p[0]=tf32r(irr[it].x); p[1]=tf32r(irr[it].y); p[2]=tf32r(irr[it].z); p[3]=tf32r(irr[it].w);
            float* q=&Js[buf][row*20+c4*4];
            q[0]=tf32r(jrr[it].x); q[1]=tf32r(jrr[it].y); q[2]=tf32r(jrr[it].z); q[3]=tf32r(jrr[it].w);
        }
    };
    const int KT = DIMD/16;   // 48
    loadg(0, ir, jr); stores(0, ir, jr); __syncthreads();
    for (int kt=0; kt<KT; kt++){
        int buf = kt&1;
        if (kt+1<KT) loadg(kt+1, ir, jr);
        #pragma unroll
        for (int ks=0; ks<16; ks+=8){
            float af[4][4], bf[4][2];
            #pragma unroll
            for (int mt=0; mt<4; mt++){
                const float* p=&Is[buf][(wm*64+mt*16+r)*20 + ks + c];
                af[mt][0]=p[0]; af[mt][1]=p[8*20]; af[mt][2]=p[4]; af[mt][3]=p[8*20+4];
            }
            #pragma unroll
            for (int nt=0; nt<4; nt++){
                const float* q=&Js[buf][(wn*32+nt*8+r)*20 + ks + c];
                bf[nt][0]=q[0]; bf[nt][1]=q[4];
            }
            #pragma unroll
            for (int mt=0; mt<4; mt++)
                #pragma unroll
                for (int nt=0; nt<4; nt++)
                    mma8(acc[mt][nt], af[mt], bf[nt]);
        }
        if (kt+1<KT){ stores((kt+1)&1, ir, jr); __syncthreads(); }
    }
    __syncthreads();
    if (tid<128){
        ssqi[tid]=g_sq[b*NTOK + ib*128 + tid];
        ssqj[tid]=g_sq[b*NTOK + jb*128 + tid];
        smax[tid]=0;
    }
    __syncthreads();
    #pragma unroll
    for (int mt=0; mt<4; mt++){
        #pragma unroll
        for (int i2=0; i2<2; i2++){
            int rl = wm*64+mt*16+r+i2*8;
            float sqi = ssqi[rl];
            float mx = 0.f;
            #pragma unroll
            for (int nt=0; nt<4; nt++){
                int cl = wn*32+nt*8+2*c;
                float d0 = sqi + ssqj[cl]   - 2.f*acc[mt][nt][i2*2+0];
                float d1 = sqi + ssqj[cl+1] - 2.f*acc[mt][nt][i2*2+1];
                d0 = sqrtf(fmaxf(d0,1e-12f));
                d1 = sqrtf(fmaxf(d1,1e-12f));
                mx = fmaxf(mx, fmaxf(d0,d1));
            }
            atomicMax(&smax[rl], __float_as_int(mx));
        }
    }
    __syncthreads();
    if (tid<128)
        atomicMax((int*)&g_m[b*NTOK + ib*128 + tid], smax[tid]);
}

// ---------------------------------------------------------------- k_gemm
// C = epilogue(gelu(A @ W + bias)); prologue optionally synthesizes cat[A | x+m]
// SRCA: 0=g_A 1=g_m1 2=g_t    DST: 0=g_m1 1=g_t 2=g_A 3=outp
// EPI : 0=gelu   1=gelu*x*m1   2=gelu*x
template<int SRCA, bool CAT, int EPI, int DST>
__global__ void __launch_bounds__(256) k_gemm(
    const float* __restrict__ Bw, const float* __restrict__ bias,
    const float* __restrict__ x, float* __restrict__ outp, int Ktot)
{
    const float* Aop = (SRCA==0)? g_A : (SRCA==1)? g_m1 : g_t;
    float* Cout = (DST==0)? g_m1 : (DST==1)? g_t : (DST==2)? g_A : outp;

    __shared__ float As[2][128*20];
    __shared__ float Bs[2][16*136];
    int tid=threadIdx.x, lane=tid&31, warp=tid>>5;
    int wm=warp&1, wn=warp>>1, r=lane>>2, c=lane&3;
    int nb=blockIdx.x, mb=blockIdx.y;

    float acc[4][4][4];
    #pragma unroll
    for (int a=0;a<4;a++)
      #pragma unroll
      for (int bb=0;bb<4;bb++)
        #pragma unroll
        for (int cc=0;cc<4;cc++) acc[a][bb][cc]=0.f;

    float4 ar[2], br[2];
    auto loadg = [&](int kt, float4* arr, float4* brr){
        #pragma unroll
        for (int it=0; it<2; it++){
            int L=tid+it*256;
            int row=L>>2, c4=L&3;
            int kg=kt*16+c4*4;
            int rg=mb*128+row;
            float4 v;
            if (!CAT || kg < DIMD){
                v = *(const float4*)(Aop + rg*DIMD + kg);
            } else {
                v = *(const float4*)(x + rg*DIMD + (kg-DIMD));
                float mm = g_m[rg];
                v.x+=mm; v.y+=mm; v.z+=mm; v.w+=mm;
            }
            arr[it]=v;
            int kr=L>>5, n4=L&31;
            brr[it] = *(const float4*)(Bw + (kt*16+kr)*DIMD + nb*128 + n4*4);
        }
    };
    auto stores = [&](int buf, float4* arr, float4* brr){
        #pragma unroll
        for (int it=0; it<2; it++){
            int L=tid+it*256, row=L>>2, c4=L&3;
            float* p=&As[buf][row*20+c4*4];
            p[0]=tf32r(arr[it].x); p[1]=tf32r(arr[it].y); p[2]=tf32r(arr[it].z); p[3]=tf32r(arr[it].w);
            int kr=L>>5, n4=L&31;
            float* q=&Bs[buf][kr*136+n4*4];
            q[0]=tf32r(brr[it].x); q[1]=tf32r(brr[it].y); q[2]=tf32r(brr[it].z); q[3]=tf32r(brr[it].w);
        }
    };
    const int KT = Ktot/16;
    loadg(0, ar, br); stores(0, ar, br); __syncthreads();
    for (int kt=0; kt<KT; kt++){
        int buf=kt&1;
        if (kt+1<KT) loadg(kt+1, ar, br);
        #pragma unroll
        for (int ks=0; ks<16; ks+=8){
            float af[4][4], bf[4][2];
            #pragma unroll
            for (int mt=0; mt<4; mt++){
                const float* p=&As[buf][(wm*64+mt*16+r)*20 + ks + c];
                af[mt][0]=p[0]; af[mt][1]=p[8*20]; af[mt][2]=p[4]; af[mt][3]=p[8*20+4];
            }
            #pragma unroll
            for (int nt=0; nt<4; nt++){
                const float* q=&Bs[buf][(ks+c)*136 + wn*32+nt*8 + r];
                bf[nt][0]=q[0]; bf[nt][1]=q[4*136];
            }
            #pragma unroll
            for (int mt=0; mt<4; mt++)
                #pragma unroll
                for (int nt=0; nt<4; nt++)
                    mma8(acc[mt][nt], af[mt], bf[nt]);
        }
        if (kt+1<KT){ stores((kt+1)&1, ar, br); __syncthreads(); }
    }
    // epilogue
    #pragma unroll
    for (int mt=0; mt<4; mt++){
        #pragma unroll
        for (int i2=0; i2<2; i2++){
            int rg = mb*128 + wm*64 + mt*16 + r + i2*8;
            #pragma unroll
            for (int nt=0; nt<4; nt++){
                int cg = nb*128 + wn*32 + nt*8 + 2*c;
                float v0 = acc[mt][nt][i2*2+0] + bias[cg];
                float v1 = acc[mt][nt][i2*2+1] + bias[cg+1];
                v0 = gelu_exact(v0); v1 = gelu_exact(v1);
                int idx = rg*DIMD + cg;
                if (EPI==1){
                    float2 xx = *(const float2*)(x+idx);
                    float2 mm = *(const float2*)(g_m1+idx);
                    v0 *= xx.x*mm.x; v1 *= xx.y*mm.y;
                } else if (EPI==2){
                    float2 xx = *(const float2*)(x+idx);
                    v0 *= xx.x; v1 *= xx.y;
                }
                *(float2*)(Cout+idx) = make_float2(v0,v1);
            }
        }
    }
}

// ---------------------------------------------------------------- launch
extern "C" void kernel_launch(void* const* d_in, const int* in_sizes, int n_in,
                              void* d_out, int out_size) {
    const float* x     = (const float*)d_in[0];
    const float* gamma = (const float*)d_in[1];
    const float* beta  = (const float*)d_in[2];
    const float* w1 = (const float*)d_in[3];
    const float* b1 = (const float*)d_in[4];
    const float* w2 = (const float*)d_in[5];
    const float* b2 = (const float*)d_in[6];
    const float* w3 = (const float*)d_in[7];
    const float* b3 = (const float*)d_in[8];
    const float* w4 = (const float*)d_in[9];
    const float* b4 = (const float*)d_in[10];
    float* out = (float*)d_out;

    k_avg<<<NB*DIMD/256, 256>>>(x);
    k_ln <<<MTOT, 256>>>(x, gamma, beta);
    k_gram<<<dim3(NTOK/128, NTOK/128, NB), 256>>>();
    dim3 gg(DIMD/128, MTOT/128);
    // layer1: m1 = gelu([A | x+m] @ w1 + b1)
    k_gemm<0,true ,0,0><<<gg,256>>>(w1, b1, x, nullptr, 2*DIMD);
    // layer2: t = m1 * x * gelu(m1 @ w2 + b2)
    k_gemm<1,false,1,1><<<gg,256>>>(w2, b2, x, nullptr, DIMD);
    // layer3: (reuse g_A) = x * gelu(t @ w3 + b3)
    k_gemm<2,false,2,2><<<gg,256>>>(w3, b3, x, nullptr, DIMD);
    // layer4: out = gelu((x*l3) @ w4 + b4)
    k_gemm<0,false,0,3><<<gg,256>>>(w4, b4, x, out, DIMD);
}